// round 5
// baseline (speedup 1.0000x reference)
#include <cuda_runtime.h>
#include <cstdint>

// ---------------------------------------------------------------------------
// Single-block fused kernel, warp-local end-to-end:
//   warp w owns batches {2w, 2w+1}. It scans them for class presence AND
//   computes their 12 BCE terms, so the mask -> loss dependency never leaves
//   the warp. Only the final 32-partial sum crosses warps (one __syncthreads).
//
// Latency hiding: the log terms depend only on se_pred, so they are computed
// WHILE the target int4 load is in flight. After the load lands the work is:
// redux.or -> predicated select -> short shfl reduce.
//
// Presence scan: 16 lanes per batch, int4 loads -> 64 labels/batch/iter.
// Early exit is valid because presence-OR is monotone (skipped data cannot
// change the result); uniform labels finish in 1 iter
// (p_miss(64) ~ 5e-5 per batch), adversarial data degrades to a full scan.
// ---------------------------------------------------------------------------
__global__ void __launch_bounds__(1024, 1)
se_loss_warp_kernel(const int* __restrict__ target,
                    const float* __restrict__ se_pred,
                    float* __restrict__ out,
                    int n_vec4_per_batch, int n_batches, int n_terms) {
    const int tid     = threadIdx.x;
    const int wid     = tid >> 5;
    const int lane    = tid & 31;
    const int half    = lane >> 4;        // scan role: which batch of the pair
    const int sublane = lane & 15;

    __shared__ float spartial[32];

    const int n_pairs = (n_batches + 1) >> 1;   // 32 for B=64
    float warp_sum = 0.0f;                      // this warp's loss partial

    for (int bpair = wid; bpair < n_pairs; bpair += 32) {
        const int b_scan = (bpair << 1) + half;         // batch this lane scans
        const bool scan_valid = (b_scan < n_batches);
        const int shamt = half << 4;

        // --- issue first target load immediately ---
        const int4* __restrict__ t4 = reinterpret_cast<const int4*>(target)
                                      + (long long)b_scan * n_vec4_per_batch;
        int4 v0;
        if (scan_valid && sublane < n_vec4_per_batch) v0 = t4[sublane];

        // --- overlap: per-lane BCE log terms (lanes 0..11) ---
        // lane -> (batch = 2*bpair + lane/6, class = lane%6)
        const int term_idx = bpair * 12 + lane;          // global term id
        const bool term_valid = (lane < 12) && (term_idx < n_terms);
        float v_present = 0.0f, v_absent = 0.0f;
        int t_shift = 0;
        if (term_valid) {
            const float p = se_pred[term_idx];
            v_present = -fmaxf(logf(p),    -100.0f);
            v_absent  = -fmaxf(log1pf(-p), -100.0f);
            const int bhalf = (lane >= 6);
            t_shift = (bhalf << 4) + (lane - bhalf * 6);  // bit of packed mask
        }

        // --- finish scan: OR labels, early-exit loop ---
        const unsigned DONE = 0x003F003Fu;
        unsigned acc = scan_valid ? 0u : (0x3Fu << shamt);
        if (scan_valid && sublane < n_vec4_per_batch) {
            unsigned bits = (1u << (v0.x & 31)) | (1u << (v0.y & 31)) |
                            (1u << (v0.z & 31)) | (1u << (v0.w & 31));
            acc |= (bits & 0x3Fu) << shamt;
        }
        acc = __reduce_or_sync(0xffffffffu, acc);
        if ((acc & DONE) != DONE) {
            const int max_iter = (n_vec4_per_batch + 15) >> 4;
            for (int it = 1; it < max_iter; it++) {
                int idx = (it << 4) + sublane;
                if (scan_valid && idx < n_vec4_per_batch) {
                    int4 v = t4[idx];
                    unsigned bits = (1u << (v.x & 31)) | (1u << (v.y & 31)) |
                                    (1u << (v.z & 31)) | (1u << (v.w & 31));
                    acc |= (bits & 0x3Fu) << shamt;
                }
                acc = __reduce_or_sync(0xffffffffu, acc);
                if ((acc & DONE) == DONE) break;
            }
        }

        // --- select term value from the now-known packed masks ---
        float v = 0.0f;
        if (term_valid)
            v = ((acc >> t_shift) & 1u) ? v_present : v_absent;

        // reduce 12 lanes (lanes 12..31 carry 0)
        #pragma unroll
        for (int o = 8; o > 0; o >>= 1) v += __shfl_down_sync(0xffffffffu, v, o);
        if (lane == 0) warp_sum += v;
    }

    if (lane == 0) spartial[wid] = warp_sum;
    __syncthreads();

    // --- final: warp 0 sums the 32 partials ---
    if (tid < 32) {
        float s = spartial[tid];
        #pragma unroll
        for (int o = 16; o > 0; o >>= 1) s += __shfl_down_sync(0xffffffffu, s, o);
        if (tid == 0) out[0] = s / (float)n_terms;
    }
}

// ---------------------------------------------------------------------------
extern "C" void kernel_launch(void* const* d_in, const int* in_sizes, int n_in,
                              void* d_out, int out_size) {
    // Resolve inputs by size: se_pred has 64*6 = 384 elements; target is huge.
    int se_idx = 0, tg_idx = 1;
    if (n_in >= 2 && in_sizes[0] > in_sizes[1]) { se_idx = 1; tg_idx = 0; }

    const float* se_pred = (const float*)d_in[se_idx];
    const int*   target  = (const int*)d_in[tg_idx];
    float* out = (float*)d_out;

    const int n_terms   = in_sizes[se_idx];        // 384
    const int B         = n_terms / 6;             // 64
    const int per_batch = in_sizes[tg_idx] / B;    // 262144 int32 labels
    const int n_vec4    = per_batch / 4;           // int4 count per batch

    se_loss_warp_kernel<<<1, 1024>>>(target, se_pred, out, n_vec4, B, n_terms);
}